// round 17
// baseline (speedup 1.0000x reference)
#include <cuda_runtime.h>
#include <cstdint>
#include <math.h>

#define COL 14
#define NJ 23
#define PAIR_ELEMS (COL * COL)   // 196
#define WARPS_PER_BLOCK 8
#define BLOCK_THREADS (WARPS_PER_BLOCK * 32)
#define CHUNK 10                 // 94208/(8*10) -> 1178 blocks ~ one wave

__device__ float        g_sum   = 0.0f;
__device__ unsigned int g_count = 0u;

// gaussian weights exp(-k^2/2)/sum, k=-4..4 (normalized in double, cast to f32)
__device__ __constant__ float c_w[9] = {
    0.000133832f, 0.00443186f, 0.05399111f, 0.24197140f, 0.39894345f,
    0.24197140f, 0.05399111f, 0.00443186f, 0.000133832f
};

// ---- packed f32x2 helpers (sm_103a FFMA2/FMUL2/FADD2 via PTX) ----
__device__ __forceinline__ unsigned long long pk2(float a, float b) {
    unsigned long long r;
    asm("mov.b64 %0, {%1, %2};" : "=l"(r) : "f"(a), "f"(b));
    return r;
}
__device__ __forceinline__ void fma2(unsigned long long& d,
                                     unsigned long long a, unsigned long long b) {
    asm("fma.rn.f32x2 %0, %1, %2, %0;" : "+l"(d) : "l"(a), "l"(b));
}
__device__ __forceinline__ void add2(unsigned long long& d, unsigned long long a) {
    asm("add.rn.f32x2 %0, %1, %0;" : "+l"(d) : "l"(a));
}
__device__ __forceinline__ unsigned long long mul2(unsigned long long a,
                                                   unsigned long long b) {
    unsigned long long r;
    asm("mul.rn.f32x2 %0, %1, %2;" : "=l"(r) : "l"(a), "l"(b));
    return r;
}
__device__ __forceinline__ float2 upk2(unsigned long long p) {
    float2 f;
    asm("mov.b64 {%0, %1}, %2;" : "=f"(f.x), "=f"(f.y) : "l"(p));
    return f;
}

__device__ __forceinline__ void amax_node(float& v, int& i, float vr, int ir) {
    if (vr > v) { v = vr; i = ir; }   // strict >: ties keep smaller index
}
__device__ __forceinline__ void prefetch_l1(const void* p) {
    asm volatile("prefetch.global.L1 [%0];" :: "l"(p));
}

__global__ __launch_bounds__(BLOCK_THREADS, 8)
void mse3d_kernel(const float* __restrict__ o,
                  const float* __restrict__ h,
                  const float* __restrict__ t,
                  const int*   __restrict__ v,
                  float* __restrict__ out,
                  int n_pairs, int nblocks) {
    __shared__ __align__(16) float sMt[PAIR_ELEMS];   // [i*COL+r] = M[r][i]
    __shared__ float sColMin[COL], sColMax[COL];
    __shared__ float sColS1[COL], sColS2[COL];
    __shared__ float wsum[WARPS_PER_BLOCK];

    const int tid = threadIdx.x;

    // ---- per-block gaussian matrix build ----
    if (tid < PAIR_ELEMS) {
        const int outr = tid / COL;
        const int i    = tid % COL;
        float m = 0.0f;
        #pragma unroll
        for (int k = -4; k <= 4; k++) {
            int ii = (outr + k + 2 * COL) % (2 * COL);
            if (ii >= COL) ii = 2 * COL - 1 - ii;
            if (ii == i) m += c_w[k + 4];
        }
        sMt[i * COL + outr] = m;
    }
    __syncthreads();
    if (tid < COL) {
        float mn = INFINITY, mx = -INFINITY, s1 = 0.0f, s2 = 0.0f;
        #pragma unroll
        for (int r = 0; r < COL; r++) {
            float val = sMt[tid * COL + r];   // M[r][tid]
            mn = fminf(mn, val);
            mx = fmaxf(mx, val);
            s1 += val;
            s2 = fmaf(val, val, s2);
        }
        sColMin[tid] = mn;
        sColMax[tid] = mx;
        sColS1[tid]  = s1;
        sColS2[tid]  = s2;
    }
    __syncthreads();

    const int lane  = tid & 31;
    const int warp  = tid >> 5;
    const int gwarp = blockIdx.x * WARPS_PER_BLOCK + warp;
    const int pair0 = gwarp * CHUNK;
    const int cnt   = min(CHUNK, n_pairs - pair0);

    float acc  = 0.0f;                 // scalar d1 cross terms
    float acc2 = 0.0f;                 // d2 + per-pair constants
    unsigned long long accp = 0ull;    // packed sum of h^2

    if (cnt > 0) {
        const bool hasb = (lane < 17);     // second float4 (idx 32+lane < 49)

        // per-lane sub-pair coordinates (each (q,q+1) shares a row; c even)
        const int ea  = 4 * lane;
        const int r0a = ea / COL,       c0a = ea - r0a * COL;
        const int r1a = (ea + 2) / COL, c1a = (ea + 2) - r1a * COL;
        const int eb  = 4 * (32 + lane);
        const int r0b = eb / COL,       c0b = eb - r0b * COL;
        const int r1b = (eb + 2) / COL, c1b = (eb + 2) - r1b * COL;

        const float4* hbase = (const float4*)(h + (size_t)pair0 * PAIR_ELEMS);

        // ---- per-chunk t/v load (coalesced) ----
        const float tl = (lane < 3 * cnt) ? t[(size_t)pair0 * 3 + lane] : 0.0f;
        const int   vl = (lane < cnt) ? v[(size_t)(pair0 + lane) * 2] : 0;

        // ---- pre-pass: lane m holds pair m's packed params ----
        // pparam = xc | yc<<4 | mask<<8 ; pinv = -2*inv ; pnb = -2*nb
        // warp-uniform sum(tt^2) constant folds into acc2 here (once).
        int   pparam = 0;
        float pinv = 0.0f, pnb = 0.0f;
        {
            const int tli = (int)truncf(tl * (float)COL);
            const int xi = __shfl_sync(0xffffffffu, tli, (3 * lane) & 31);
            const int yi = __shfl_sync(0xffffffffu, tli, (3 * lane + 1) & 31);
            if (lane < cnt) {
                const bool in_range = (xi >= 0) && (xi <= COL - 1) &&
                                      (yi >= 0) && (yi <= COL - 1);
                const bool mask = (vl == 1) && in_range;
                const int xc = min(max(xi, 0), COL - 1);
                const int yc = min(max(yi, 0), COL - 1);
                pparam = xc | (yc << 4) | (mask ? (1 << 8) : 0);
                if (mask) {
                    const float mn  = sColMin[yc] * sColMin[xc];
                    const float mx  = sColMax[yc] * sColMax[xc];
                    const float inv = 1.0f / (mx - mn);
                    const float nb  = -mn * inv;
                    pinv = -2.0f * inv;
                    pnb  = -2.0f * nb;
                    const float S1 = sColS1[yc] * sColS1[xc];
                    const float S2 = sColS2[yc] * sColS2[xc];
                    float ct = inv * inv * S2;
                    ct = fmaf(2.0f * inv * nb, S1, ct);
                    ct = fmaf((float)PAIR_ELEMS * nb, nb, ct);
                    acc2 += ct;
                }
            }
        }

        // warm L1 for pair 0
        prefetch_l1(hbase + lane);
        if (hasb) prefetch_l1(hbase + 32 + lane);

        int myAmax = 0;   // lane k banks pair k's argmax

        // ================= Phase 1: h-only (d1 + argmax) =================
        for (int k = 0; k < cnt; k++) {
            const float4* hp = hbase + (size_t)k * 49;
            float4 va = hp[lane];
            float4 vb = hasb ? hp[32 + lane] : make_float4(0.f, 0.f, 0.f, 0.f);

            // prefetch next pair's tile into L1 (zero-register pipelining)
            if (k + 1 < cnt) {
                prefetch_l1(hp + 49 + lane);
                if (hasb) prefetch_l1(hp + 49 + 32 + lane);
            }

            // single packed-param broadcast per pair
            const int pp = __shfl_sync(0xffffffffu, pparam, k);

            // ---- tree argmax over the 8 local elements ----
            float m0 = va.x; int i0 = ea;
            amax_node(m0, i0, va.y, ea + 1);
            float m1 = va.z; int i1 = ea + 2;
            amax_node(m1, i1, va.w, ea + 3);
            float m2 = vb.x; int i2 = eb;
            amax_node(m2, i2, vb.y, eb + 1);
            float m3 = vb.z; int i3 = eb + 2;
            amax_node(m3, i3, vb.w, eb + 3);
            amax_node(m0, i0, m1, i1);
            amax_node(m2, i2, m3, i3);
            amax_node(m0, i0, m2, i2);
            // h >= 0: bits order-isomorphic; first occurrence via min-index
            const unsigned int bbits = __float_as_uint(m0);
            const unsigned int mbits = __reduce_max_sync(0xffffffffu, bbits);
            const int amax = (int)__reduce_min_sync(
                0xffffffffu, (bbits == mbits) ? (unsigned)i0 : 0xffffffffu);
            if (lane == k) myAmax = amax;

            // packed h values (reused for h^2 and masked path)
            const unsigned long long pa01 = pk2(va.x, va.y);
            const unsigned long long pa23 = pk2(va.z, va.w);
            const unsigned long long pb01 = pk2(vb.x, vb.y);
            const unsigned long long pb23 = pk2(vb.z, vb.w);

            // ---- always: sum h^2 (packed, 4 FFMA2) ----
            fma2(accp, pa01, pa01);
            fma2(accp, pa23, pa23);
            fma2(accp, pb01, pb01);   // zeros when !hasb
            fma2(accp, pb23, pb23);

            // ---- masked path: cross term only (constants pre-folded) ----
            if (pp & (1 << 8)) {                      // warp-uniform branch
                const float ninv2 = __shfl_sync(0xffffffffu, pinv, k);
                const float nnb2  = __shfl_sync(0xffffffffu, pnb,  k);
                const int xc = pp & 15;
                const int yc = (pp >> 4) & 15;
                const float* gy = &sMt[yc * COL];
                const float* gx = &sMt[xc * COL];

                unsigned long long hw2 = 0ull, sh2 = 0ull;
                {
                    const float2 g0 = *(const float2*)(gx + c0a);  // c even -> aligned
                    const float2 g1 = *(const float2*)(gx + c1a);
                    const float gy0 = gy[r0a], gy1 = gy[r1a];
                    fma2(hw2, pa01, mul2(pk2(gy0, gy0), pk2(g0.x, g0.y)));
                    fma2(hw2, pa23, mul2(pk2(gy1, gy1), pk2(g1.x, g1.y)));
                    add2(sh2, pa01);
                    add2(sh2, pa23);
                }
                if (hasb) {
                    const float2 g0 = *(const float2*)(gx + c0b);
                    const float2 g1 = *(const float2*)(gx + c1b);
                    const float gy0 = gy[r0b], gy1 = gy[r1b];
                    fma2(hw2, pb01, mul2(pk2(gy0, gy0), pk2(g0.x, g0.y)));
                    fma2(hw2, pb23, mul2(pk2(gy1, gy1), pk2(g1.x, g1.y)));
                    add2(sh2, pb01);
                    add2(sh2, pb23);
                }
                const float2 hwf = upk2(hw2);
                const float2 shf = upk2(sh2);
                acc = fmaf(ninv2, hwf.x + hwf.y, acc);
                acc = fmaf(nnb2,  shf.x + shf.y, acc);
            }
        }

        // ====== Phase 2: all o-gathers at once (up to 30 concurrent) ======
        {
            const int kq = min(lane / 3, cnt - 1);     // clamped for shfl
            const int am = __shfl_sync(0xffffffffu, myAmax, kq);
            if (lane < 3 * cnt) {
                const int k    = lane / 3;
                const int comp = lane - 3 * k;
                const int pair = pair0 + k;
                const int b    = pair / NJ;
                const int j    = pair - b * NJ;
                const int ayk  = am / COL;
                const int axk  = am - ayk * COL;
                const int row  = b * (3 * NJ) + j + comp * NJ;
                const float ov = __ldg(o + ((size_t)row * PAIR_ELEMS + am));
                const float scale = 1.0f / (float)COL;
                const float addv = (comp == 0) ? (float)axk * scale
                                 : ((comp == 1) ? (float)ayk * scale : 0.0f);
                const float d = ov + addv - tl;        // tl == t[pair*3+comp]
                acc2 = fmaf(d, d, acc2);
            }
        }
    }

    {
        const float2 ap = upk2(accp);
        acc += ap.x + ap.y + acc2;
    }

    // ---- block reduction ----
    #pragma unroll
    for (int off = 16; off > 0; off >>= 1)
        acc += __shfl_down_sync(0xffffffffu, acc, off);
    if (lane == 0) wsum[warp] = acc;
    __syncthreads();

    if (warp == 0) {
        float s = (lane < WARPS_PER_BLOCK) ? wsum[lane] : 0.0f;
        #pragma unroll
        for (int off = WARPS_PER_BLOCK / 2; off > 0; off >>= 1)
            s += __shfl_down_sync(0xffffffffu, s, off);
        if (lane == 0) {
            atomicAdd(&g_sum, s * (1.0f / (float)NJ));
            __threadfence();
            unsigned int done = atomicAdd(&g_count, 1u);
            if (done == (unsigned)nblocks - 1) {
                float total = atomicExch(&g_sum, 0.0f);
                out[0] = total;
                g_count = 0u;
                __threadfence();
            }
        }
    }
}

extern "C" void kernel_launch(void* const* d_in, const int* in_sizes, int n_in,
                              void* d_out, int out_size) {
    const float* o = (const float*)d_in[0];
    const float* h = (const float*)d_in[1];
    const float* t = (const float*)d_in[2];
    const int*   v = (const int*)d_in[3];
    float* out = (float*)d_out;

    const int n_pairs = in_sizes[1] / PAIR_ELEMS;   // B * NJ from h
    const int pairs_per_block = WARPS_PER_BLOCK * CHUNK;
    const int blocks = (n_pairs + pairs_per_block - 1) / pairs_per_block;

    mse3d_kernel<<<blocks, BLOCK_THREADS>>>(o, h, t, v, out, n_pairs, blocks);
}